// round 15
// baseline (speedup 1.0000x reference)
#include <cuda_runtime.h>

#define SDIM 56
#define NCELL 3136
#define NITEM 6272
#define NCLS 20
#define IMG_STRIDE 94080
#define CONF_OFF 62720
#define COORD_OFF 68992
#define MAXOUT 30
#define NCAND 256
#define KEYBUF 2048
#define BATCH 256
#define NT 512
#define SCORE_FLOOR 0.884765625f   // 906/1024, exact in fp32

__device__ __forceinline__ float pmax20(const float4* cp)
{
    float4 v0 = cp[0], v1 = cp[1], v2 = cp[2], v3 = cp[3], v4 = cp[4];
    float m01 = fmaxf(fmaxf(v0.x, v0.y), fmaxf(v0.z, v0.w));
    float m11 = fmaxf(fmaxf(v1.x, v1.y), fmaxf(v1.z, v1.w));
    float m21 = fmaxf(fmaxf(v2.x, v2.y), fmaxf(v2.z, v2.w));
    float m31 = fmaxf(fmaxf(v3.x, v3.y), fmaxf(v3.z, v3.w));
    float m41 = fmaxf(fmaxf(v4.x, v4.y), fmaxf(v4.z, v4.w));
    return fmaxf(fmaxf(fmaxf(m01, m11), fmaxf(m21, m31)), m41);
}

// rare path: exact reference-order argmax of cf*p[c]
__device__ __forceinline__ void exact_argmax(const float4* cp, float cf,
                                             float* bout, int* aout)
{
    float b = -1.0f; int a = 0;
    #pragma unroll
    for (int k = 0; k < 5; ++k) {
        float4 v = cp[k];
        float vv[4] = {v.x, v.y, v.z, v.w};
        #pragma unroll
        for (int u = 0; u < 4; ++u) {
            float p = cf * vv[u];
            if (p > b) { b = p; a = 4 * k + u; }
        }
    }
    *bout = b; *aout = a;
}

// ---------------------------------------------------------------------------
// Fully fused kernel: one block per image. decode -> filter -> sort -> NMS.
// ---------------------------------------------------------------------------
__global__ __launch_bounds__(NT, 2) void detect_fused(const float* __restrict__ in,
                                                      float* __restrict__ out)
{
    __shared__ __align__(16) unsigned long long keys[KEYBUF]; // cand list / sort dbl-buf
    __shared__ __align__(16) float4 sbox[NCAND];
    __shared__ float sscore[NCAND];
    __shared__ float scls[NCAND];
    __shared__ int spicks[MAXOUT];
    __shared__ int s_cnt;

    const int img = blockIdx.x;
    const int t = threadIdx.x;
    const int lane = t & 31;
    const float* base  = in + (long)img * IMG_STRIDE;
    const float* coord = base + COORD_OFF;

    if (t == 0) s_cnt = 0;
    __syncthreads();

    // ---- Phase 1: stream-decode + filter (2-cell pipeline, pmax identity) ----
    for (int c0 = t; c0 < NCELL; c0 += 2 * NT) {
        const int cA = c0;
        const int cB = c0 + NT;
        const bool hasB = (cB < NCELL);

        const float4* cpA = (const float4*)(base + cA * NCLS);
        const float4* cpB = (const float4*)(base + (hasB ? cB : cA) * NCLS);
        const float2 cfA = *(const float2*)(base + CONF_OFF + cA * 2);
        const float2 cfB = *(const float2*)(base + CONF_OFF + (hasB ? cB : cA) * 2);

        // both cells' loads issue before either max-tree completes
        float pmA = pmax20(cpA);
        float pmB = pmax20(cpB);

        // exact screening scores (RN-mul monotone: fmul(cf,pmax) == max_c fmul(cf,p[c]))
        float mA0 = cfA.x * pmA, mA1 = cfA.y * pmA;
        float mB0 = hasB ? cfB.x * pmB : 0.0f;
        float mB1 = hasB ? cfB.y * pmB : 0.0f;

        if (mA0 >= SCORE_FLOOR) {
            float b; int a2;
            exact_argmax(cpA, cfA.x, &b, &a2);
            int pos = atomicAdd(&s_cnt, 1);
            if (pos < KEYBUF)
                keys[pos] = ((unsigned long long)__float_as_uint(b) << 18) |
                            ((unsigned long long)(8191 - cA * 2) << 5) |
                            (unsigned long long)a2;
        }
        if (mA1 >= SCORE_FLOOR) {
            float b; int a2;
            exact_argmax(cpA, cfA.y, &b, &a2);
            int pos = atomicAdd(&s_cnt, 1);
            if (pos < KEYBUF)
                keys[pos] = ((unsigned long long)__float_as_uint(b) << 18) |
                            ((unsigned long long)(8191 - (cA * 2 + 1)) << 5) |
                            (unsigned long long)a2;
        }
        if (mB0 >= SCORE_FLOOR) {
            float b; int a2;
            exact_argmax(cpB, cfB.x, &b, &a2);
            int pos = atomicAdd(&s_cnt, 1);
            if (pos < KEYBUF)
                keys[pos] = ((unsigned long long)__float_as_uint(b) << 18) |
                            ((unsigned long long)(8191 - cB * 2) << 5) |
                            (unsigned long long)a2;
        }
        if (mB1 >= SCORE_FLOOR) {
            float b; int a2;
            exact_argmax(cpB, cfB.y, &b, &a2);
            int pos = atomicAdd(&s_cnt, 1);
            if (pos < KEYBUF)
                keys[pos] = ((unsigned long long)__float_as_uint(b) << 18) |
                            ((unsigned long long)(8191 - (cB * 2 + 1)) << 5) |
                            (unsigned long long)a2;
        }
    }
    __syncthreads();
    int n = s_cnt; if (n > KEYBUF) n = KEYBUF;

    // ---- Phase 2: bitonic sort descending ----
    int np = NT; while (np < n) np <<= 1;
    unsigned long long a;
    if (np == NT) {
        a = (t < n) ? keys[t] : 0ull;
        __syncthreads();
        int phase = 0;
        #pragma unroll
        for (int k = 2; k <= NT; k <<= 1) {
            #pragma unroll
            for (int j = k >> 1; j > 0; j >>= 1) {
                bool up = ((t & k) == 0);
                unsigned long long b2;
                if (j >= 32) {
                    keys[phase * NT + t] = a;
                    __syncthreads();
                    b2 = keys[phase * NT + (t ^ j)];
                    phase ^= 1;
                } else {
                    b2 = __shfl_xor_sync(0xFFFFFFFFu, a, j);
                }
                bool keep_max = (up == ((t & j) == 0));
                bool amax = (a > b2);
                a = (keep_max == amax) ? a : b2;
            }
        }
    } else {
        // in-place smem fallback for 512 < n <= 2048 (not taken on expected data)
        for (int i = n + t; i < np; i += NT) keys[i] = 0ull;
        __syncthreads();
        for (int k = 2; k <= np; k <<= 1) {
            for (int j = k >> 1; j > 0; j >>= 1) {
                for (int i = t; i < np; i += NT) {
                    int ixj = i ^ j;
                    if (ixj > i) {
                        unsigned long long x = keys[i];
                        unsigned long long y = keys[ixj];
                        bool up = ((i & k) == 0);
                        bool doswap = up ? (x < y) : (x > y);
                        if (doswap) { keys[i] = y; keys[ixj] = x; }
                    }
                }
                __syncthreads();
            }
        }
        a = keys[t];
    }

    // ---- Phase 3: build top-256 SoA ----
    if (t < NCAND) {
        int idx = 8191 - (int)((a >> 5) & 0x1FFFull);
        float s = __uint_as_float((unsigned)(a >> 18));
        float y0 = 0.f, x0 = 0.f, y1 = 0.f, x1 = 0.f, cl = 0.f;
        if (idx < NITEM) {
            int cell = idx >> 1;
            int bb = idx & 1;
            int ci = cell / SDIM;
            int cj = cell - ci * SDIM;
            float4 cd = *(const float4*)(coord + ((long)cell * 2 + bb) * 4);
            float x = __fdiv_rn(cd.x + (float)cj, 56.0f);
            float y = __fdiv_rn(cd.y + (float)ci, 56.0f);
            float wh = (cd.z * cd.z) * 0.5f;
            float hh = (cd.w * cd.w) * 0.5f;
            y0 = y - hh; x0 = x - wh; y1 = y + hh; x1 = x + wh;
            cl = (float)(unsigned)(a & 31ull);
        } else {
            s = 0.0f;
        }
        sbox[t] = make_float4(y0, x0, y1, x1);
        sscore[t] = s;
        scls[t] = cl;
    }
    __syncthreads();
    if (t >= 32) return;                    // only warp 0 continues

    // ---- Phase 4: barrier-free greedy NMS on warp 0 ----
    float4 B[8];
    float A[8];
    #pragma unroll
    for (int k = 0; k < 8; ++k) {
        int r = k * 32 + lane;
        float4 b = sbox[r];
        B[k] = b;
        A[k] = __fmul_rn(fmaxf(b.z - b.x, 0.0f), fmaxf(b.w - b.y, 0.0f));
    }
    unsigned mask = 0xFFu;
    for (int r = 0; r < MAXOUT; ++r) {
        int kf = __ffs(mask);
        int rank = kf ? ((kf - 1) * 32 + lane) : 0x7FFFFFFF;
        rank = __reduce_min_sync(0xFFFFFFFFu, rank);         // min rank == argmax score
        int p = (rank < NCAND) ? rank : -1;
        if (lane == 0) spicks[r] = p;
        if (p >= 0) {
            float4 pb = sbox[p];
            float parea = __fmul_rn(fmaxf(pb.z - pb.x, 0.0f), fmaxf(pb.w - pb.y, 0.0f));
            #pragma unroll
            for (int k = 0; k < 8; ++k) {
                float iy = fmaxf(0.0f, fminf(pb.z, B[k].z) - fmaxf(pb.x, B[k].x));
                float ix = fmaxf(0.0f, fminf(pb.w, B[k].w) - fmaxf(pb.y, B[k].y));
                float inter = __fmul_rn(iy, ix);
                float uni = parea + A[k] - inter;
                float rhs = __fmul_rn(0.4f, uni);
                float diff = inter - rhs;
                bool sup;
                if (fabsf(diff) <= 4e-7f * uni) {            // borderline (~never): exact
                    float iou = (uni > 0.0f) ? __fdiv_rn(inter, uni) : 0.0f;
                    sup = iou > 0.4f;
                } else {
                    sup = (uni > 0.0f) && (diff > 0.0f);
                }
                if (sup) mask &= ~(1u << k);
            }
            if (lane == (p & 31)) mask &= ~(1u << (p >> 5));
        }
    }
    __syncwarp();

    // ---- output ----
    if (lane < MAXOUT) {
        int p = spicks[lane];
        float* o = out + (long)img * (MAXOUT * 6) + lane * 6;
        if (p >= 0) {
            float4 b = sbox[p];
            o[0] = b.x; o[1] = b.y; o[2] = b.z; o[3] = b.w;
            o[4] = sscore[p]; o[5] = scls[p];
        } else {
            o[0] = 0.f; o[1] = 0.f; o[2] = 0.f; o[3] = 0.f; o[4] = 0.f; o[5] = 0.f;
        }
    }
}

extern "C" void kernel_launch(void* const* d_in, const int* in_sizes, int n_in,
                              void* d_out, int out_size)
{
    const float* in = (const float*)d_in[0];
    float* out = (float*)d_out;
    detect_fused<<<BATCH, NT>>>(in, out);
}

// round 16
// speedup vs baseline: 1.0099x; 1.0099x over previous
#include <cuda_runtime.h>

#define SDIM 56
#define NCELL 3136
#define NITEM 6272
#define NCLS 20
#define IMG_STRIDE 94080
#define CONF_OFF 62720
#define COORD_OFF 68992
#define MAXOUT 30
#define NCAND 256
#define KEYBUF 2048
#define BATCH 256
#define NT 512
#define SCORE_FLOOR 0.884765625f   // 906/1024, exact in fp32

__device__ __forceinline__ float pmax20(const float4* cp)
{
    float4 v0 = cp[0], v1 = cp[1], v2 = cp[2], v3 = cp[3], v4 = cp[4];
    float m01 = fmaxf(fmaxf(v0.x, v0.y), fmaxf(v0.z, v0.w));
    float m11 = fmaxf(fmaxf(v1.x, v1.y), fmaxf(v1.z, v1.w));
    float m21 = fmaxf(fmaxf(v2.x, v2.y), fmaxf(v2.z, v2.w));
    float m31 = fmaxf(fmaxf(v3.x, v3.y), fmaxf(v3.z, v3.w));
    float m41 = fmaxf(fmaxf(v4.x, v4.y), fmaxf(v4.z, v4.w));
    return fmaxf(fmaxf(fmaxf(m01, m11), fmaxf(m21, m31)), m41);
}

// rare path: exact reference-order argmax of cf*p[c]
__device__ __forceinline__ void exact_argmax(const float4* cp, float cf,
                                             float* bout, int* aout)
{
    float b = -1.0f; int a = 0;
    #pragma unroll
    for (int k = 0; k < 5; ++k) {
        float4 v = cp[k];
        float vv[4] = {v.x, v.y, v.z, v.w};
        #pragma unroll
        for (int u = 0; u < 4; ++u) {
            float p = cf * vv[u];
            if (p > b) { b = p; a = 4 * k + u; }
        }
    }
    *bout = b; *aout = a;
}

// ---------------------------------------------------------------------------
// Fully fused kernel: one block per image. decode -> filter -> sort -> NMS.
// ---------------------------------------------------------------------------
__global__ __launch_bounds__(NT, 2) void detect_fused(const float* __restrict__ in,
                                                      float* __restrict__ out)
{
    __shared__ __align__(16) unsigned long long keys[KEYBUF]; // cand list / sort dbl-buf
    __shared__ __align__(16) float4 sbox[NCAND];
    __shared__ float sscore[NCAND];
    __shared__ float scls[NCAND];
    __shared__ int spicks[MAXOUT];
    __shared__ int s_cnt;

    const int img = blockIdx.x;
    const int t = threadIdx.x;
    const int lane = t & 31;
    const float* base  = in + (long)img * IMG_STRIDE;
    const float* coord = base + COORD_OFF;

    if (t == 0) s_cnt = 0;
    __syncthreads();

    // ---- Phase 1: stream-decode + filter (2-cell pipeline, pmax identity) ----
    for (int c0 = t; c0 < NCELL; c0 += 2 * NT) {
        const int cA = c0;
        const int cB = c0 + NT;
        const bool hasB = (cB < NCELL);

        const float4* cpA = (const float4*)(base + cA * NCLS);
        const float4* cpB = (const float4*)(base + (hasB ? cB : cA) * NCLS);
        const float2 cfA = *(const float2*)(base + CONF_OFF + cA * 2);
        const float2 cfB = *(const float2*)(base + CONF_OFF + (hasB ? cB : cA) * 2);

        float pmA = pmax20(cpA);
        float pmB = pmax20(cpB);

        // exact screening (RN-mul monotone: fmul(cf,pmax) == max_c fmul(cf,p[c]))
        float mA0 = cfA.x * pmA, mA1 = cfA.y * pmA;
        float mB0 = hasB ? cfB.x * pmB : 0.0f;
        float mB1 = hasB ? cfB.y * pmB : 0.0f;

        if (mA0 >= SCORE_FLOOR) {
            float b; int a2;
            exact_argmax(cpA, cfA.x, &b, &a2);
            int pos = atomicAdd(&s_cnt, 1);
            if (pos < KEYBUF)
                keys[pos] = ((unsigned long long)__float_as_uint(b) << 18) |
                            ((unsigned long long)(8191 - cA * 2) << 5) |
                            (unsigned long long)a2;
        }
        if (mA1 >= SCORE_FLOOR) {
            float b; int a2;
            exact_argmax(cpA, cfA.y, &b, &a2);
            int pos = atomicAdd(&s_cnt, 1);
            if (pos < KEYBUF)
                keys[pos] = ((unsigned long long)__float_as_uint(b) << 18) |
                            ((unsigned long long)(8191 - (cA * 2 + 1)) << 5) |
                            (unsigned long long)a2;
        }
        if (mB0 >= SCORE_FLOOR) {
            float b; int a2;
            exact_argmax(cpB, cfB.x, &b, &a2);
            int pos = atomicAdd(&s_cnt, 1);
            if (pos < KEYBUF)
                keys[pos] = ((unsigned long long)__float_as_uint(b) << 18) |
                            ((unsigned long long)(8191 - cB * 2) << 5) |
                            (unsigned long long)a2;
        }
        if (mB1 >= SCORE_FLOOR) {
            float b; int a2;
            exact_argmax(cpB, cfB.y, &b, &a2);
            int pos = atomicAdd(&s_cnt, 1);
            if (pos < KEYBUF)
                keys[pos] = ((unsigned long long)__float_as_uint(b) << 18) |
                            ((unsigned long long)(8191 - (cB * 2 + 1)) << 5) |
                            (unsigned long long)a2;
        }
    }
    __syncthreads();
    int n = s_cnt; if (n > KEYBUF) n = KEYBUF;

    // ---- Phase 2: bitonic sort descending ----
    int np = NT; while (np < n) np <<= 1;
    unsigned long long a;
    if (np == NT) {
        a = (t < n) ? keys[t] : 0ull;
        __syncthreads();
        int phase = 0;
        #pragma unroll
        for (int k = 2; k <= NT; k <<= 1) {
            #pragma unroll
            for (int j = k >> 1; j > 0; j >>= 1) {
                bool up = ((t & k) == 0);
                unsigned long long b2;
                if (j >= 32) {
                    keys[phase * NT + t] = a;
                    __syncthreads();
                    b2 = keys[phase * NT + (t ^ j)];
                    phase ^= 1;
                } else {
                    b2 = __shfl_xor_sync(0xFFFFFFFFu, a, j);
                }
                bool keep_max = (up == ((t & j) == 0));
                bool amax = (a > b2);
                a = (keep_max == amax) ? a : b2;
            }
        }
    } else {
        // in-place smem fallback for 512 < n <= 2048 (not taken on expected data)
        for (int i = n + t; i < np; i += NT) keys[i] = 0ull;
        __syncthreads();
        for (int k = 2; k <= np; k <<= 1) {
            for (int j = k >> 1; j > 0; j >>= 1) {
                for (int i = t; i < np; i += NT) {
                    int ixj = i ^ j;
                    if (ixj > i) {
                        unsigned long long x = keys[i];
                        unsigned long long y = keys[ixj];
                        bool up = ((i & k) == 0);
                        bool doswap = up ? (x < y) : (x > y);
                        if (doswap) { keys[i] = y; keys[ixj] = x; }
                    }
                }
                __syncthreads();
            }
        }
        a = keys[t];
    }

    // ---- Phase 3: build top-256 SoA ----
    if (t < NCAND) {
        int idx = 8191 - (int)((a >> 5) & 0x1FFFull);
        float s = __uint_as_float((unsigned)(a >> 18));
        float y0 = 0.f, x0 = 0.f, y1 = 0.f, x1 = 0.f, cl = 0.f;
        if (idx < NITEM) {
            int cell = idx >> 1;
            int bb = idx & 1;
            int ci = cell / SDIM;
            int cj = cell - ci * SDIM;
            float4 cd = *(const float4*)(coord + ((long)cell * 2 + bb) * 4);
            float x = __fdiv_rn(cd.x + (float)cj, 56.0f);
            float y = __fdiv_rn(cd.y + (float)ci, 56.0f);
            float wh = (cd.z * cd.z) * 0.5f;
            float hh = (cd.w * cd.w) * 0.5f;
            y0 = y - hh; x0 = x - wh; y1 = y + hh; x1 = x + wh;
            cl = (float)(unsigned)(a & 31ull);
        } else {
            s = 0.0f;
        }
        sbox[t] = make_float4(y0, x0, y1, x1);
        sscore[t] = s;
        scls[t] = cl;
    }
    __syncthreads();
    if (t >= 32) return;                    // only warp 0 continues

    // ---- Phase 4: barrier-free greedy NMS on warp 0, straight-line rounds ----
    float4 B[8];
    float A[8];
    #pragma unroll
    for (int k = 0; k < 8; ++k) {
        int r = k * 32 + lane;
        float4 b = sbox[r];
        B[k] = b;
        A[k] = __fmul_rn(fmaxf(b.z - b.x, 0.0f), fmaxf(b.w - b.y, 0.0f));
    }
    unsigned mask = 0xFFu;
    for (int r = 0; r < MAXOUT; ++r) {
        int kf = __ffs(mask);
        int rank = kf ? ((kf - 1) * 32 + lane) : 0x7FFFFFFF;
        rank = __reduce_min_sync(0xFFFFFFFFu, rank);         // min rank == argmax score
        int p = (rank < NCAND) ? rank : -1;
        if (lane == 0) spicks[r] = p;
        if (p >= 0) {
            float4 pb = sbox[p];                             // uniform LDS broadcast
            float parea = __fmul_rn(fmaxf(pb.z - pb.x, 0.0f), fmaxf(pb.w - pb.y, 0.0f));
            unsigned newmask = mask;
            bool border = false;
            #pragma unroll
            for (int k = 0; k < 8; ++k) {
                float iy = fmaxf(0.0f, fminf(pb.z, B[k].z) - fmaxf(pb.x, B[k].x));
                float ix = fmaxf(0.0f, fminf(pb.w, B[k].w) - fmaxf(pb.y, B[k].y));
                float inter = __fmul_rn(iy, ix);
                float uni = parea + A[k] - inter;
                float diff = inter - __fmul_rn(0.4f, uni);
                // branchless fast decision (predicated LOP, no BSSY)
                bool sup = (uni > 0.0f) & (diff > 0.0f);
                border |= ((mask >> k) & 1u) && (fabsf(diff) <= 4e-7f * uni);
                newmask &= ~(((unsigned)sup) << k);
            }
            // warp-uniform, statistically never-taken exact fallback
            if (__any_sync(0xFFFFFFFFu, border)) {
                newmask = mask;
                #pragma unroll
                for (int k = 0; k < 8; ++k) {
                    float iy = fmaxf(0.0f, fminf(pb.z, B[k].z) - fmaxf(pb.x, B[k].x));
                    float ix = fmaxf(0.0f, fminf(pb.w, B[k].w) - fmaxf(pb.y, B[k].y));
                    float inter = __fmul_rn(iy, ix);
                    float uni = parea + A[k] - inter;
                    float iou = (uni > 0.0f) ? __fdiv_rn(inter, uni) : 0.0f;
                    if (iou > 0.4f) newmask &= ~(1u << k);
                }
            }
            mask = newmask;
            if (lane == (p & 31)) mask &= ~(1u << (p >> 5)); // clear pick itself
        }
    }
    __syncwarp();

    // ---- output ----
    if (lane < MAXOUT) {
        int p = spicks[lane];
        float* o = out + (long)img * (MAXOUT * 6) + lane * 6;
        if (p >= 0) {
            float4 b = sbox[p];
            o[0] = b.x; o[1] = b.y; o[2] = b.z; o[3] = b.w;
            o[4] = sscore[p]; o[5] = scls[p];
        } else {
            o[0] = 0.f; o[1] = 0.f; o[2] = 0.f; o[3] = 0.f; o[4] = 0.f; o[5] = 0.f;
        }
    }
}

extern "C" void kernel_launch(void* const* d_in, const int* in_sizes, int n_in,
                              void* d_out, int out_size)
{
    const float* in = (const float*)d_in[0];
    float* out = (float*)d_out;
    detect_fused<<<BATCH, NT>>>(in, out);
}

// round 17
// speedup vs baseline: 1.1429x; 1.1316x over previous
#include <cuda_runtime.h>

#define SDIM 56
#define NCELL 3136
#define NITEM 6272
#define NCLS 20
#define IMG_STRIDE 94080
#define CONF_OFF 62720
#define COORD_OFF 68992
#define MAXOUT 30
#define NCAND 256
#define KEYBUF 2048
#define BATCH 256
#define NT 512
#define SCORE_FLOOR 0.884765625f   // 906/1024, exact in fp32

__device__ __forceinline__ float pmax20(const float4* cp)
{
    float4 v0 = cp[0], v1 = cp[1], v2 = cp[2], v3 = cp[3], v4 = cp[4];
    float m01 = fmaxf(fmaxf(v0.x, v0.y), fmaxf(v0.z, v0.w));
    float m11 = fmaxf(fmaxf(v1.x, v1.y), fmaxf(v1.z, v1.w));
    float m21 = fmaxf(fmaxf(v2.x, v2.y), fmaxf(v2.z, v2.w));
    float m31 = fmaxf(fmaxf(v3.x, v3.y), fmaxf(v3.z, v3.w));
    float m41 = fmaxf(fmaxf(v4.x, v4.y), fmaxf(v4.z, v4.w));
    return fmaxf(fmaxf(fmaxf(m01, m11), fmaxf(m21, m31)), m41);
}

// rare path: exact reference-order argmax of cf*p[c]
__device__ __forceinline__ void exact_argmax(const float4* cp, float cf,
                                             float* bout, int* aout)
{
    float b = -1.0f; int a = 0;
    #pragma unroll
    for (int k = 0; k < 5; ++k) {
        float4 v = cp[k];
        float vv[4] = {v.x, v.y, v.z, v.w};
        #pragma unroll
        for (int u = 0; u < 4; ++u) {
            float p = cf * vv[u];
            if (p > b) { b = p; a = 4 * k + u; }
        }
    }
    *bout = b; *aout = a;
}

// ---------------------------------------------------------------------------
// Fully fused kernel: one block per image. decode -> filter -> rank -> NMS.
// ---------------------------------------------------------------------------
__global__ __launch_bounds__(NT, 2) void detect_fused(const float* __restrict__ in,
                                                      float* __restrict__ out)
{
    __shared__ __align__(16) unsigned long long keys[KEYBUF + 4]; // cand list (+vec pad)
    __shared__ __align__(16) float4 sbox[NCAND];
    __shared__ float sscore[NCAND];
    __shared__ float scls[NCAND];
    __shared__ int spicks[MAXOUT];
    __shared__ int s_cnt;

    const int img = blockIdx.x;
    const int t = threadIdx.x;
    const int lane = t & 31;
    const float* base  = in + (long)img * IMG_STRIDE;
    const float* coord = base + COORD_OFF;

    if (t == 0) s_cnt = 0;
    __syncthreads();

    // ---- Phase 1: stream-decode + filter (2-cell pipeline, pmax identity) ----
    for (int c0 = t; c0 < NCELL; c0 += 2 * NT) {
        const int cA = c0;
        const int cB = c0 + NT;
        const bool hasB = (cB < NCELL);

        const float4* cpA = (const float4*)(base + cA * NCLS);
        const float4* cpB = (const float4*)(base + (hasB ? cB : cA) * NCLS);
        const float2 cfA = *(const float2*)(base + CONF_OFF + cA * 2);
        const float2 cfB = *(const float2*)(base + CONF_OFF + (hasB ? cB : cA) * 2);

        float pmA = pmax20(cpA);
        float pmB = pmax20(cpB);

        // exact screening (RN-mul monotone: fmul(cf,pmax) == max_c fmul(cf,p[c]))
        float mA0 = cfA.x * pmA, mA1 = cfA.y * pmA;
        float mB0 = hasB ? cfB.x * pmB : 0.0f;
        float mB1 = hasB ? cfB.y * pmB : 0.0f;

        if (mA0 >= SCORE_FLOOR) {
            float b; int a2;
            exact_argmax(cpA, cfA.x, &b, &a2);
            int pos = atomicAdd(&s_cnt, 1);
            if (pos < KEYBUF)
                keys[pos] = ((unsigned long long)__float_as_uint(b) << 18) |
                            ((unsigned long long)(8191 - cA * 2) << 5) |
                            (unsigned long long)a2;
        }
        if (mA1 >= SCORE_FLOOR) {
            float b; int a2;
            exact_argmax(cpA, cfA.y, &b, &a2);
            int pos = atomicAdd(&s_cnt, 1);
            if (pos < KEYBUF)
                keys[pos] = ((unsigned long long)__float_as_uint(b) << 18) |
                            ((unsigned long long)(8191 - (cA * 2 + 1)) << 5) |
                            (unsigned long long)a2;
        }
        if (mB0 >= SCORE_FLOOR) {
            float b; int a2;
            exact_argmax(cpB, cfB.x, &b, &a2);
            int pos = atomicAdd(&s_cnt, 1);
            if (pos < KEYBUF)
                keys[pos] = ((unsigned long long)__float_as_uint(b) << 18) |
                            ((unsigned long long)(8191 - cB * 2) << 5) |
                            (unsigned long long)a2;
        }
        if (mB1 >= SCORE_FLOOR) {
            float b; int a2;
            exact_argmax(cpB, cfB.y, &b, &a2);
            int pos = atomicAdd(&s_cnt, 1);
            if (pos < KEYBUF)
                keys[pos] = ((unsigned long long)__float_as_uint(b) << 18) |
                            ((unsigned long long)(8191 - (cB * 2 + 1)) << 5) |
                            (unsigned long long)a2;
        }
    }
    __syncthreads();
    int n = s_cnt; if (n > KEYBUF) n = KEYBUF;   // uniform post-barrier

    // pad 4 zero keys for vectorized overshoot; zero-fill SoA slots beyond n
    if (t < 4) keys[n + t] = 0ull;
    for (int r = n + t; r < NCAND; r += NT) {
        sbox[r] = make_float4(0.f, 0.f, 0.f, 0.f);
        sscore[r] = 0.f; scls[r] = 0.f;
    }
    __syncthreads();

    // ---- Phase 2: barrier-free rank-by-counting (replaces bitonic sort) ----
    // rank(i) = #{j : key[j] > key[i]}; keys distinct => permutation;
    // slot 'rank' == sorted position => identical to previous sort output.
    const int n4 = (n + 3) & ~3;
    for (int i = t; i < n; i += NT) {
        const unsigned long long ki = keys[i];
        int rank = 0;
        for (int j = 0; j < n4; j += 4) {              // broadcast LDS.128 pairs
            ulonglong2 k01 = *(const ulonglong2*)&keys[j];
            ulonglong2 k23 = *(const ulonglong2*)&keys[j + 2];
            rank += (int)(k01.x > ki) + (int)(k01.y > ki)
                  + (int)(k23.x > ki) + (int)(k23.y > ki);
        }
        if (rank < NCAND) {
            // decode winner key -> SoA slot 'rank'
            int idx = 8191 - (int)((ki >> 5) & 0x1FFFull);
            float s = __uint_as_float((unsigned)(ki >> 18));
            int cell = idx >> 1;
            int bb = idx & 1;
            int ci = cell / SDIM;
            int cj = cell - ci * SDIM;
            float4 cd = *(const float4*)(coord + ((long)cell * 2 + bb) * 4);
            float x = __fdiv_rn(cd.x + (float)cj, 56.0f);
            float y = __fdiv_rn(cd.y + (float)ci, 56.0f);
            float wh = (cd.z * cd.z) * 0.5f;
            float hh = (cd.w * cd.w) * 0.5f;
            sbox[rank] = make_float4(y - hh, x - wh, y + hh, x + wh);
            sscore[rank] = s;
            scls[rank] = (float)(unsigned)(ki & 31ull);
        }
    }
    __syncthreads();
    if (t >= 32) return;                    // only warp 0 continues

    // ---- Phase 3: barrier-free greedy NMS on warp 0, straight-line rounds ----
    float4 B[8];
    float A[8];
    #pragma unroll
    for (int k = 0; k < 8; ++k) {
        int r = k * 32 + lane;
        float4 b = sbox[r];
        B[k] = b;
        A[k] = __fmul_rn(fmaxf(b.z - b.x, 0.0f), fmaxf(b.w - b.y, 0.0f));
    }
    unsigned mask = 0xFFu;
    for (int r = 0; r < MAXOUT; ++r) {
        int kf = __ffs(mask);
        int rank = kf ? ((kf - 1) * 32 + lane) : 0x7FFFFFFF;
        rank = __reduce_min_sync(0xFFFFFFFFu, rank);         // min rank == argmax score
        int p = (rank < NCAND) ? rank : -1;
        if (lane == 0) spicks[r] = p;
        if (p >= 0) {
            float4 pb = sbox[p];                             // uniform LDS broadcast
            float parea = __fmul_rn(fmaxf(pb.z - pb.x, 0.0f), fmaxf(pb.w - pb.y, 0.0f));
            unsigned newmask = mask;
            bool border = false;
            #pragma unroll
            for (int k = 0; k < 8; ++k) {
                float iy = fmaxf(0.0f, fminf(pb.z, B[k].z) - fmaxf(pb.x, B[k].x));
                float ix = fmaxf(0.0f, fminf(pb.w, B[k].w) - fmaxf(pb.y, B[k].y));
                float inter = __fmul_rn(iy, ix);
                float uni = parea + A[k] - inter;
                float diff = inter - __fmul_rn(0.4f, uni);
                bool sup = (uni > 0.0f) & (diff > 0.0f);     // predicated, no branch
                border |= ((mask >> k) & 1u) && (fabsf(diff) <= 4e-7f * uni);
                newmask &= ~(((unsigned)sup) << k);
            }
            if (__any_sync(0xFFFFFFFFu, border)) {           // ~never taken; exact path
                newmask = mask;
                #pragma unroll
                for (int k = 0; k < 8; ++k) {
                    float iy = fmaxf(0.0f, fminf(pb.z, B[k].z) - fmaxf(pb.x, B[k].x));
                    float ix = fmaxf(0.0f, fminf(pb.w, B[k].w) - fmaxf(pb.y, B[k].y));
                    float inter = __fmul_rn(iy, ix);
                    float uni = parea + A[k] - inter;
                    float iou = (uni > 0.0f) ? __fdiv_rn(inter, uni) : 0.0f;
                    if (iou > 0.4f) newmask &= ~(1u << k);
                }
            }
            mask = newmask;
            if (lane == (p & 31)) mask &= ~(1u << (p >> 5)); // clear pick itself
        }
    }
    __syncwarp();

    // ---- output ----
    if (lane < MAXOUT) {
        int p = spicks[lane];
        float* o = out + (long)img * (MAXOUT * 6) + lane * 6;
        if (p >= 0) {
            float4 b = sbox[p];
            o[0] = b.x; o[1] = b.y; o[2] = b.z; o[3] = b.w;
            o[4] = sscore[p]; o[5] = scls[p];
        } else {
            o[0] = 0.f; o[1] = 0.f; o[2] = 0.f; o[3] = 0.f; o[4] = 0.f; o[5] = 0.f;
        }
    }
}

extern "C" void kernel_launch(void* const* d_in, const int* in_sizes, int n_in,
                              void* d_out, int out_size)
{
    const float* in = (const float*)d_in[0];
    float* out = (float*)d_out;
    detect_fused<<<BATCH, NT>>>(in, out);
}